// round 9
// baseline (speedup 1.0000x reference)
#include <cuda_runtime.h>

#define NRr 2048
#define NDd 2048
#define NCMc 32
#define THREADS 256   // 8 days per thread via 256-bit loads

__device__ __forceinline__ float softplus_f(float x) {
    // softplus via MUFU: max(x,0) + log(1 + exp(-|x|)); ample accuracy vs 1e-3
    return fmaxf(x, 0.0f) + __logf(1.0f + __expf(-fabsf(x)));
}

// 256-bit global load (LDG.E.256 on sm_100+)
__device__ __forceinline__ void ldg256(const float* p, float v[8]) {
    asm("ld.global.v8.f32 {%0,%1,%2,%3,%4,%5,%6,%7}, [%8];"
        : "=f"(v[0]), "=f"(v[1]), "=f"(v[2]), "=f"(v[3]),
          "=f"(v[4]), "=f"(v[5]), "=f"(v[6]), "=f"(v[7])
        : "l"(p));
}

__global__ __launch_bounds__(THREADS, 4)
void rwm_kernel(const float* __restrict__ CM_Alpha,
                const float* __restrict__ Wearing_Alpha,
                const float* __restrict__ Mobility_Alpha,
                const float* __restrict__ RegionR,
                const float* __restrict__ GI_mean,
                const float* __restrict__ GI_sd,
                const float* __restrict__ InitialSize_log,
                const float* __restrict__ noise,
                const float* __restrict__ psi,
                const float* __restrict__ NPIs,
                const float* __restrict__ wear,
                const float* __restrict__ mob,
                float* __restrict__ out)
{
    __shared__ float s_cm[NCMc];
    __shared__ float s_warp[8];

    const int r    = blockIdx.x;
    const int t    = threadIdx.x;
    const int lane = t & 31;
    const int wid  = t >> 5;

    if (t < NCMc) s_cm[t] = CM_Alpha[t];
    __syncthreads();

    const size_t rowOff = (size_t)r * NDd;
    const int d0 = t * 8;

    // ---- hot loop: 32 streams of LDG.E.256 (8KB contiguous per warp req) ----
    float acc[8];
    #pragma unroll
    for (int j = 0; j < 8; ++j) acc[j] = 0.0f;

    const float* np = NPIs + (size_t)r * NCMc * NDd + d0;
    #pragma unroll
    for (int c = 0; c < NCMc; ++c) {
        float v[8];
        ldg256(np + (size_t)c * NDd, v);
        const float a = s_cm[c];
        #pragma unroll
        for (int j = 0; j < 8; ++j) acc[j] = fmaf(a, v[j], acc[j]);
    }

    // scalars + aux streams after the loop
    const float wA   = Wearing_Alpha[0];
    const float mA   = Mobility_Alpha[0];
    const float gm   = GI_mean[0];
    const float gs   = GI_sd[0];
    const float gs2  = gs * gs;
    const float gi_beta      = __expf(gm / gs2);
    const float inv_gi_alpha = gs2 / (gm * gm);
    const float rr    = __expf(psi[0]);
    const float regR  = RegionR[r];
    const float initL = InitialSize_log[r];
    const float sp0 = softplus_f(mA * __ldg(mob + rowOff));

    float wv[8], mv[8], nv[8];
    ldg256(wear  + rowOff + d0, wv);
    ldg256(mob   + rowOff + d0, mv);
    ldg256(noise + rowOff + d0, nv);

    // per-day growth = gi_beta + exp(ExpectedLogR)/gi_alpha + noise,
    // then thread-local inclusive prefix over the 8 owned days
    float p[8];
    float run = 0.0f;
    #pragma unroll
    for (int k = 0; k < 8; ++k) {
        const float elr = regR - acc[k] - wA * wv[k]
                        - (softplus_f(mA * mv[k]) - sp0);
        const float g = fmaf(__expf(elr), inv_gi_alpha, gi_beta) + nv[k];
        run += g;
        p[k] = run;
    }

    // warp-level inclusive scan of per-thread totals
    float v = run;
    #pragma unroll
    for (int o = 1; o < 32; o <<= 1) {
        const float n = __shfl_up_sync(0xffffffffu, v, o);
        if (lane >= o) v += n;
    }
    if (lane == 31) s_warp[wid] = v;
    __syncthreads();

    // single-barrier cross-warp fixup over 8 warp totals
    float ws = (lane < 8) ? s_warp[lane] : 0.0f;
    #pragma unroll
    for (int o = 1; o < 8; o <<= 1) {
        const float n = __shfl_up_sync(0xffffffffu, ws, o);
        if (lane >= o) ws += n;
    }
    const float warpOff = (wid > 0)
        ? __shfl_sync(0xffffffffu, ws, wid - 1) : 0.0f;
    const float excl = warpOff + (v - run);  // exclusive prefix for this thread

    // p = r / (r + exp(LogInfected)) + 1e-8
    const float base = initL + excl;
    float4 lo, hi;
    lo.x = __fdividef(rr, rr + __expf(base + p[0])) + 1e-8f;
    lo.y = __fdividef(rr, rr + __expf(base + p[1])) + 1e-8f;
    lo.z = __fdividef(rr, rr + __expf(base + p[2])) + 1e-8f;
    lo.w = __fdividef(rr, rr + __expf(base + p[3])) + 1e-8f;
    hi.x = __fdividef(rr, rr + __expf(base + p[4])) + 1e-8f;
    hi.y = __fdividef(rr, rr + __expf(base + p[5])) + 1e-8f;
    hi.z = __fdividef(rr, rr + __expf(base + p[6])) + 1e-8f;
    hi.w = __fdividef(rr, rr + __expf(base + p[7])) + 1e-8f;
    __stcs((float4*)(out + rowOff + d0),     lo);
    __stcs((float4*)(out + rowOff + d0 + 4), hi);
}

extern "C" void kernel_launch(void* const* d_in, const int* in_sizes, int n_in,
                              void* d_out, int out_size)
{
    const float* CM_Alpha        = (const float*)d_in[0];
    const float* Wearing_Alpha   = (const float*)d_in[1];
    const float* Mobility_Alpha  = (const float*)d_in[2];
    const float* RegionR         = (const float*)d_in[3];
    const float* GI_mean         = (const float*)d_in[4];
    const float* GI_sd           = (const float*)d_in[5];
    const float* InitialSize_log = (const float*)d_in[6];
    const float* noise           = (const float*)d_in[7];
    const float* psi             = (const float*)d_in[8];
    const float* NPIs            = (const float*)d_in[9];
    const float* wear            = (const float*)d_in[10];
    const float* mobility        = (const float*)d_in[11];
    float* out = (float*)d_out;

    rwm_kernel<<<NRr, THREADS>>>(CM_Alpha, Wearing_Alpha, Mobility_Alpha,
                                 RegionR, GI_mean, GI_sd, InitialSize_log,
                                 noise, psi, NPIs, wear, mobility, out);
}